// round 5
// baseline (speedup 1.0000x reference)
#include <cuda_runtime.h>
#include <cuda_bf16.h>
#include <cstdint>

// Problem constants
#define B_  4
#define N_  2048
#define E_  1024
#define H_  16
#define D_  64
#define BH_ (B_*H_)          // 64
#define M_  (B_*N_)          // 8192 rows for the projections

// ---------------- scratch (device globals; no allocations allowed) ----------
__device__ float g_q[(size_t)BH_ * N_ * D_];   // [b*H+h][n][d]  32MB
__device__ float g_k[(size_t)BH_ * N_ * D_];   // 32MB
__device__ float g_v[(size_t)BH_ * N_ * D_];   // 32MB
__device__ float g_o[(size_t)M_ * E_];         // [b*N+n][h*64+d] 32MB

__device__ __forceinline__ float neg_inf() { return __int_as_float(0xff800000); }

// ============================================================================
// SGEMM: 128x128 block tile, BK=16, 256 threads, 8x8 per-thread micro tile
// ============================================================================
#define BM 128
#define BN 128
#define BK 16

// ---- Kernel 1: QKV = X @ W_qkv + b_qkv, scattered into g_q/g_k/g_v ---------
__global__ void __launch_bounds__(256)
qkv_gemm_kernel(const float* __restrict__ X, const float* __restrict__ W,
                const float* __restrict__ bias)
{
    __shared__ float As[BK][BM + 4];
    __shared__ float Bs[BK][BN];

    const int tid = threadIdx.x;
    const int tx = tid & 15, ty = tid >> 4;
    const int m0 = blockIdx.y * BM;
    const int n0 = blockIdx.x * BN;
    const int ldb = 3 * E_;   // 3072

    float acc[8][8];
#pragma unroll
    for (int i = 0; i < 8; i++)
#pragma unroll
        for (int j = 0; j < 8; j++) acc[i][j] = 0.f;

    for (int k0 = 0; k0 < E_; k0 += BK) {
#pragma unroll
        for (int j = 0; j < 2; j++) {          // A tile: 128x16 = 512 float4
            int f = tid + j * 256;
            int row = f >> 2;
            int c4 = (f & 3) * 4;
            float4 v = *(const float4*)(X + (size_t)(m0 + row) * E_ + k0 + c4);
            As[c4 + 0][row] = v.x; As[c4 + 1][row] = v.y;
            As[c4 + 2][row] = v.z; As[c4 + 3][row] = v.w;
        }
#pragma unroll
        for (int j = 0; j < 2; j++) {          // B tile: 16x128 = 512 float4
            int f = tid + j * 256;
            int row = f >> 5;
            int c4 = (f & 31) * 4;
            *(float4*)&Bs[row][c4] =
                *(const float4*)(W + (size_t)(k0 + row) * ldb + n0 + c4);
        }
        __syncthreads();

#pragma unroll
        for (int k = 0; k < BK; k++) {
            float a[8], b[8];
            *(float4*)&a[0] = *(float4*)&As[k][ty * 8];
            *(float4*)&a[4] = *(float4*)&As[k][ty * 8 + 4];
            *(float4*)&b[0] = *(float4*)&Bs[k][tx * 8];
            *(float4*)&b[4] = *(float4*)&Bs[k][tx * 8 + 4];
#pragma unroll
            for (int i = 0; i < 8; i++)
#pragma unroll
                for (int j = 0; j < 8; j++)
                    acc[i][j] = fmaf(a[i], b[j], acc[i][j]);
        }
        __syncthreads();
    }

    // Epilogue: bias + scatter to q/k/v in [b*H+h][n][d]
#pragma unroll
    for (int i = 0; i < 8; i++) {
        int gm = m0 + ty * 8 + i;
        int bb = gm >> 11;          // / 2048
        int n  = gm & 2047;
#pragma unroll
        for (int j = 0; j < 8; j++) {
            int gc = n0 + tx * 8 + j;
            float v = acc[i][j] + bias[gc];
            int which = gc >> 10;       // 0=q,1=k,2=v
            int rem   = gc & 1023;
            int h = rem >> 6;
            int d = rem & 63;
            float* dst = (which == 0) ? g_q : (which == 1) ? g_k : g_v;
            dst[(((size_t)(bb * H_ + h)) * N_ + n) * D_ + d] = v;
        }
    }
}

// ---- Kernel 3: out = O @ W_out + b_out  (plain row-major) -------------------
__global__ void __launch_bounds__(256)
out_gemm_kernel(const float* __restrict__ W, const float* __restrict__ bias,
                float* __restrict__ out)
{
    __shared__ float As[BK][BM + 4];
    __shared__ float Bs[BK][BN];

    const int tid = threadIdx.x;
    const int tx = tid & 15, ty = tid >> 4;
    const int m0 = blockIdx.y * BM;
    const int n0 = blockIdx.x * BN;

    float acc[8][8];
#pragma unroll
    for (int i = 0; i < 8; i++)
#pragma unroll
        for (int j = 0; j < 8; j++) acc[i][j] = 0.f;

    for (int k0 = 0; k0 < E_; k0 += BK) {
#pragma unroll
        for (int j = 0; j < 2; j++) {
            int f = tid + j * 256;
            int row = f >> 2;
            int c4 = (f & 3) * 4;
            float4 v = *(const float4*)(g_o + (size_t)(m0 + row) * E_ + k0 + c4);
            As[c4 + 0][row] = v.x; As[c4 + 1][row] = v.y;
            As[c4 + 2][row] = v.z; As[c4 + 3][row] = v.w;
        }
#pragma unroll
        for (int j = 0; j < 2; j++) {
            int f = tid + j * 256;
            int row = f >> 5;
            int c4 = (f & 31) * 4;
            *(float4*)&Bs[row][c4] =
                *(const float4*)(W + (size_t)(k0 + row) * E_ + n0 + c4);
        }
        __syncthreads();

#pragma unroll
        for (int k = 0; k < BK; k++) {
            float a[8], b[8];
            *(float4*)&a[0] = *(float4*)&As[k][ty * 8];
            *(float4*)&a[4] = *(float4*)&As[k][ty * 8 + 4];
            *(float4*)&b[0] = *(float4*)&Bs[k][tx * 8];
            *(float4*)&b[4] = *(float4*)&Bs[k][tx * 8 + 4];
#pragma unroll
            for (int i = 0; i < 8; i++)
#pragma unroll
                for (int j = 0; j < 8; j++)
                    acc[i][j] = fmaf(a[i], b[j], acc[i][j]);
        }
        __syncthreads();
    }

#pragma unroll
    for (int i = 0; i < 8; i++) {
        int gm = m0 + ty * 8 + i;
#pragma unroll
        for (int j = 0; j < 8; j++) {
            int gc = n0 + tx * 8 + j;
            out[(size_t)gm * E_ + gc] = acc[i][j] + bias[gc];
        }
    }
}

// ============================================================================
// Kernel 2: flash attention.  grid = (N/64, B*H), 256 threads (8 warps).
// Each warp owns 8 query rows; lane owns key/dim columns {lane, lane+32}.
// smem: Qs[64][64] | Ks[64][68] | Vs[64][64] | Ps[64][64]  (66560 B dynamic)
// ============================================================================
#define ATTN_SMEM_FLOATS (64*64 + 64*68 + 64*64 + 64*64)
#define ATTN_SMEM_BYTES  (ATTN_SMEM_FLOATS * 4)

__global__ void __launch_bounds__(256)
attn_kernel(const int* __restrict__ mask)
{
    extern __shared__ float sm[];
    float* Qs = sm;                  // [64][64]
    float* Ks = Qs + 64 * 64;        // [64][68]  (pad -> conflict-free LDS.128)
    float* Vs = Ks + 64 * 68;        // [64][64]
    float* Ps = Vs + 64 * 64;        // [64][64]

    const int tid  = threadIdx.x;
    const int warp = tid >> 5;
    const int lane = tid & 31;
    const int bh = blockIdx.y;
    const int b  = bh >> 4;
    const int h  = bh & 15;
    const int q0 = blockIdx.x * 64;

    const float* qg  = g_q + ((size_t)bh * N_ + q0) * D_;
    const float* kgb = g_k + (size_t)bh * N_ * D_;
    const float* vgb = g_v + (size_t)bh * N_ * D_;
    const int*   mb  = mask + b * N_;

    // load Q tile
#pragma unroll
    for (int j = 0; j < 4; j++) {
        int f = tid + j * 256;
        int row = f >> 4;
        int c4 = (f & 15) * 4;
        *(float4*)&Qs[row * 64 + c4] = *(const float4*)(qg + row * D_ + c4);
    }

    const int r0 = warp * 8;
    const float NEG = neg_inf();
    float m_i[8], l_i[8], o0[8], o1[8];
#pragma unroll
    for (int i = 0; i < 8; i++) { m_i[i] = NEG; l_i[i] = 0.f; o0[i] = 0.f; o1[i] = 0.f; }

    for (int kt = 0; kt < N_ / 64; kt++) {
        __syncthreads();   // previous tile's consumers done before overwrite
        const float* kg = kgb + (size_t)kt * 64 * D_;
        const float* vg = vgb + (size_t)kt * 64 * D_;
#pragma unroll
        for (int j = 0; j < 4; j++) {
            int f = tid + j * 256;
            int row = f >> 4;
            int c4 = (f & 15) * 4;
            *(float4*)&Ks[row * 68 + c4] = *(const float4*)(kg + row * D_ + c4);
            *(float4*)&Vs[row * 64 + c4] = *(const float4*)(vg + row * D_ + c4);
        }
        __syncthreads();

        // ---- S = Q @ K^T (lane cols {lane, lane+32}, 8 rows) ----
        float s0[8], s1[8];
#pragma unroll
        for (int i = 0; i < 8; i++) { s0[i] = 0.f; s1[i] = 0.f; }
#pragma unroll
        for (int d4 = 0; d4 < 16; d4++) {
            float4 kv0 = *(float4*)&Ks[lane * 68 + d4 * 4];
            float4 kv1 = *(float4*)&Ks[(lane + 32) * 68 + d4 * 4];
#pragma unroll
            for (int i = 0; i < 8; i++) {
                float4 qv = *(float4*)&Qs[(r0 + i) * 64 + d4 * 4];
                s0[i] = fmaf(qv.x, kv0.x, fmaf(qv.y, kv0.y,
                        fmaf(qv.z, kv0.z, fmaf(qv.w, kv0.w, s0[i]))));
                s1[i] = fmaf(qv.x, kv1.x, fmaf(qv.y, kv1.y,
                        fmaf(qv.z, kv1.z, fmaf(qv.w, kv1.w, s1[i]))));
            }
        }

        const int mk0 = mb[kt * 64 + lane];
        const int mk1 = mb[kt * 64 + lane + 32];

        // ---- online softmax (per warp row groups) ----
#pragma unroll
        for (int i = 0; i < 8; i++) {
            float a0 = mk0 ? s0[i] * 0.5f : NEG;   // scale = 1/sqrt(A/H) = 0.5
            float a1 = mk1 ? s1[i] * 0.5f : NEG;
            float rm = fmaxf(a0, a1);
#pragma unroll
            for (int off = 16; off > 0; off >>= 1)
                rm = fmaxf(rm, __shfl_xor_sync(0xffffffffu, rm, off));
            float mn = fmaxf(m_i[i], rm);
            float p0 = (mn == NEG) ? 0.f : __expf(a0 - mn);
            float p1 = (mn == NEG) ? 0.f : __expf(a1 - mn);
            float corr = (m_i[i] == NEG) ? 0.f : __expf(m_i[i] - mn);
            float rs = p0 + p1;
#pragma unroll
            for (int off = 16; off > 0; off >>= 1)
                rs += __shfl_xor_sync(0xffffffffu, rs, off);
            l_i[i] = l_i[i] * corr + rs;
            o0[i] *= corr;
            o1[i] *= corr;
            m_i[i] = mn;
            Ps[(r0 + i) * 64 + lane]      = p0;
            Ps[(r0 + i) * 64 + lane + 32] = p1;
        }
        __syncwarp();

        // ---- O += P @ V  (lane dims {lane, lane+32}) ----
#pragma unroll
        for (int k4 = 0; k4 < 16; k4++) {
            float v0[4], v1[4];
#pragma unroll
            for (int q = 0; q < 4; q++) {
                v0[q] = Vs[(k4 * 4 + q) * 64 + lane];
                v1[q] = Vs[(k4 * 4 + q) * 64 + lane + 32];
            }
#pragma unroll
            for (int i = 0; i < 8; i++) {
                float4 pv = *(float4*)&Ps[(r0 + i) * 64 + k4 * 4];
                o0[i] = fmaf(pv.x, v0[0], fmaf(pv.y, v0[1],
                        fmaf(pv.z, v0[2], fmaf(pv.w, v0[3], o0[i]))));
                o1[i] = fmaf(pv.x, v1[0], fmaf(pv.y, v1[1],
                        fmaf(pv.z, v1[2], fmaf(pv.w, v1[3], o1[i]))));
            }
        }
    }

    // write O in [b*N+n][h*64+d] layout for the out-projection GEMM
#pragma unroll
    for (int i = 0; i < 8; i++) {
        float inv = (l_i[i] > 0.f) ? (1.0f / l_i[i]) : 0.f;
        size_t row = ((size_t)(b * N_ + q0 + r0 + i)) * E_ + h * D_;
        g_o[row + lane]      = o0[i] * inv;
        g_o[row + lane + 32] = o1[i] * inv;
    }
}

// ============================================================================
extern "C" void kernel_launch(void* const* d_in, const int* in_sizes, int n_in,
                              void* d_out, int out_size)
{
    const float* x     = (const float*)d_in[0];
    const int*   mask  = (const int*)  d_in[1];
    const float* w_qkv = (const float*)d_in[2];
    const float* b_qkv = (const float*)d_in[3];
    const float* w_out = (const float*)d_in[4];
    const float* b_out = (const float*)d_in[5];
    float* out = (float*)d_out;

    // attention kernel needs > 48KB dynamic smem; idempotent, capture-safe
    cudaFuncSetAttribute(attn_kernel,
                         cudaFuncAttributeMaxDynamicSharedMemorySize,
                         ATTN_SMEM_BYTES);

    // 1) QKV projection + scatter   (8192 x 3072 x 1024)
    qkv_gemm_kernel<<<dim3(3 * E_ / BN, M_ / BM), 256>>>(x, w_qkv, b_qkv);

    // 2) flash attention            (32 q-tiles x 64 (b,h))
    attn_kernel<<<dim3(N_ / 64, BH_), 256, ATTN_SMEM_BYTES>>>(mask);

    // 3) output projection          (8192 x 1024 x 1024)
    out_gemm_kernel<<<dim3(E_ / BN, M_ / BM), 256>>>(w_out, b_out, out);
}

// round 13
// speedup vs baseline: 1.3366x; 1.3366x over previous
#include <cuda_runtime.h>
#include <cuda_bf16.h>
#include <mma.h>
#include <cstdint>

using namespace nvcuda;

// Problem constants
#define B_  4
#define N_  2048
#define E_  1024
#define H_  16
#define D_  64
#define BH_ (B_*H_)          // 64
#define M_  (B_*N_)          // 8192 rows for the projections
#define K_  1024             // inner dim of both projections

// ---------------- scratch (device globals; no allocations allowed) ----------
// NOTE: these are ONLY referenced from device code. Passing a __device__
// symbol as a kernel argument from host code silently binds the host shadow
// (readable via ATS on GB300!) -> zeros. That was the round-8 bug.
__device__ float g_q[(size_t)BH_ * N_ * D_];   // [b*H+h][n][d]
__device__ float g_k[(size_t)BH_ * N_ * D_];
__device__ float g_v[(size_t)BH_ * N_ * D_];
__device__ float g_o[(size_t)M_ * E_];         // [b*N+n][h*64+d]

__device__ __nv_bfloat16 g_xh[(size_t)M_ * K_];
__device__ __nv_bfloat16 g_xl[(size_t)M_ * K_];
__device__ __nv_bfloat16 g_wqh[(size_t)3 * E_ * K_];   // [3072][1024] (N rows, K contig)
__device__ __nv_bfloat16 g_wql[(size_t)3 * E_ * K_];
__device__ __nv_bfloat16 g_woh[(size_t)E_ * K_];       // [1024][1024]
__device__ __nv_bfloat16 g_wol[(size_t)E_ * K_];
__device__ __nv_bfloat16 g_oh[(size_t)M_ * K_];
__device__ __nv_bfloat16 g_ol[(size_t)M_ * K_];

__device__ __forceinline__ float neg_inf() { return __int_as_float(0xff800000); }

// ============================================================================
// Conversion kernels (device globals bound INSIDE device code via template)
// ============================================================================
// SRC 0: X (arg) -> g_xh/g_xl     SRC 1: g_o -> g_oh/g_ol
template <int SRC>
__global__ void __launch_bounds__(256)
convert_hl(const float* __restrict__ Xarg, int n4)
{
    int i = blockIdx.x * 256 + threadIdx.x;
    if (i >= n4) return;
    const float* X = (SRC == 0) ? Xarg : g_o;
    __nv_bfloat16* Xh = (SRC == 0) ? g_xh : g_oh;
    __nv_bfloat16* Xl = (SRC == 0) ? g_xl : g_ol;
    float4 v = ((const float4*)X)[i];
    __nv_bfloat16 h0 = __float2bfloat16(v.x), h1 = __float2bfloat16(v.y);
    __nv_bfloat16 h2 = __float2bfloat16(v.z), h3 = __float2bfloat16(v.w);
    __nv_bfloat162 H01; H01.x = h0; H01.y = h1;
    __nv_bfloat162 H23; H23.x = h2; H23.y = h3;
    __nv_bfloat162 L01, L23;
    L01.x = __float2bfloat16(v.x - __bfloat162float(h0));
    L01.y = __float2bfloat16(v.y - __bfloat162float(h1));
    L23.x = __float2bfloat16(v.z - __bfloat162float(h2));
    L23.y = __float2bfloat16(v.w - __bfloat162float(h3));
    ((__nv_bfloat162*)Xh)[2*i]   = H01;
    ((__nv_bfloat162*)Xh)[2*i+1] = H23;
    ((__nv_bfloat162*)Xl)[2*i]   = L01;
    ((__nv_bfloat162*)Xl)[2*i+1] = L23;
}

// W [R][C] row-major fp32 (arg, real device ptr) -> [C][R] bf16 hi/lo globals
// DST 0: g_wqh/g_wql     DST 1: g_woh/g_wol
template <int DST>
__global__ void __launch_bounds__(256)
transpose_convert(const float* __restrict__ W, int R, int C)
{
    __nv_bfloat16* Th = (DST == 0) ? g_wqh : g_woh;
    __nv_bfloat16* Tl = (DST == 0) ? g_wql : g_wol;
    __shared__ float t[32][33];
    int c0 = blockIdx.x * 32, r0 = blockIdx.y * 32;
    int tx = threadIdx.x, ty = threadIdx.y;     // 32 x 8
#pragma unroll
    for (int i = 0; i < 32; i += 8)
        t[ty + i][tx] = W[(size_t)(r0 + ty + i) * C + c0 + tx];
    __syncthreads();
#pragma unroll
    for (int i = 0; i < 32; i += 8) {
        float v = t[tx][ty + i];
        __nv_bfloat16 h = __float2bfloat16(v);
        size_t o = (size_t)(c0 + ty + i) * R + r0 + tx;
        Th[o] = h;
        Tl[o] = __float2bfloat16(v - __bfloat162float(h));
    }
}

// ============================================================================
// WMMA bf16x3 GEMM: out[M x NTOT] = A[M x 1024] @ B^T + bias
//   A: hi/lo bf16 [M][1024] row-major.  B: hi/lo bf16 [NTOT][1024] (K contig
//   == col_major fragments).  CTA tile 128x128, K-chunk 32, 256 threads,
//   8 warps in 2x4 grid, warp tile 64x32 (4x2 m16n16k16 fragments).
//   MODE 0: A=g_xh/g_xl, B=g_wqh/g_wql, scatter into g_q/g_k/g_v.
//   MODE 1: A=g_oh/g_ol, B=g_woh/g_wol, row-major into `out` (d_out).
// ============================================================================
#define LDT 40                        // bf16 smem tile stride (80B rows)
#define TILE_ELEMS (128 * LDT)
#define LDS_ 132                      // fp32 stage stride
#define GT_SMEM_BYTES (128 * LDS_ * 4)   // 67584 >= 4 tiles (40960B)

template <int MODE>
__global__ void __launch_bounds__(256, 2)
tc_gemm(const float* __restrict__ bias, float* __restrict__ out)
{
    const __nv_bfloat16* Ah = (MODE == 0) ? g_xh : g_oh;
    const __nv_bfloat16* Al = (MODE == 0) ? g_xl : g_ol;
    const __nv_bfloat16* Bh = (MODE == 0) ? g_wqh : g_woh;
    const __nv_bfloat16* Bl = (MODE == 0) ? g_wql : g_wol;
    const int NTOT = (MODE == 0) ? 3 * E_ : E_;

    extern __shared__ __align__(16) char smem[];
    __nv_bfloat16* sAh = (__nv_bfloat16*)smem;
    __nv_bfloat16* sAl = sAh + TILE_ELEMS;
    __nv_bfloat16* sBh = sAl + TILE_ELEMS;
    __nv_bfloat16* sBl = sBh + TILE_ELEMS;
    float* st = (float*)smem;                       // reused stage [128][132]

    const int tid = threadIdx.x;
    const int wid = tid >> 5;
    const int wr = wid & 1;        // warp row: 0..1  (64 rows each)
    const int wc = wid >> 1;       // warp col: 0..3  (32 cols each)
    const int m0 = blockIdx.y * 128;
    const int n0 = blockIdx.x * 128;

    wmma::fragment<wmma::accumulator, 16, 16, 16, float> acc[4][2];
#pragma unroll
    for (int i = 0; i < 4; i++)
#pragma unroll
        for (int j = 0; j < 2; j++) wmma::fill_fragment(acc[i][j], 0.0f);

    for (int k0 = 0; k0 < K_; k0 += 32) {
#pragma unroll
        for (int t = 0; t < 2; t++) {
            int f = tid + t * 256;           // 0..511
            int row = f >> 2;
            int seg = f & 3;                 // seg*8 bf16 within 32-col chunk
            size_t ga = (size_t)(m0 + row) * K_ + k0 + seg * 8;
            size_t gb = (size_t)(n0 + row) * K_ + k0 + seg * 8;
            *(uint4*)(sAh + row * LDT + seg * 8) = *(const uint4*)(Ah + ga);
            *(uint4*)(sAl + row * LDT + seg * 8) = *(const uint4*)(Al + ga);
            *(uint4*)(sBh + row * LDT + seg * 8) = *(const uint4*)(Bh + gb);
            *(uint4*)(sBl + row * LDT + seg * 8) = *(const uint4*)(Bl + gb);
        }
        __syncthreads();

#pragma unroll
        for (int ks = 0; ks < 2; ks++) {
            wmma::fragment<wmma::matrix_b, 16, 16, 16, __nv_bfloat16, wmma::col_major> bh[2], bl[2];
#pragma unroll
            for (int j = 0; j < 2; j++) {
                wmma::load_matrix_sync(bh[j], sBh + (wc * 32 + j * 16) * LDT + ks * 16, LDT);
                wmma::load_matrix_sync(bl[j], sBl + (wc * 32 + j * 16) * LDT + ks * 16, LDT);
            }
#pragma unroll
            for (int i = 0; i < 4; i++) {
                wmma::fragment<wmma::matrix_a, 16, 16, 16, __nv_bfloat16, wmma::row_major> ah, al;
                wmma::load_matrix_sync(ah, sAh + (wr * 64 + i * 16) * LDT + ks * 16, LDT);
                wmma::load_matrix_sync(al, sAl + (wr * 64 + i * 16) * LDT + ks * 16, LDT);
#pragma unroll
                for (int j = 0; j < 2; j++) {
                    wmma::mma_sync(acc[i][j], ah, bh[j], acc[i][j]);   // hi*hi
                    wmma::mma_sync(acc[i][j], ah, bl[j], acc[i][j]);   // hi*lo
                    wmma::mma_sync(acc[i][j], al, bh[j], acc[i][j]);   // lo*hi
                }
            }
        }
        __syncthreads();   // tiles consumed before refill / stage reuse
    }

    // epilogue: fragments -> smem stage -> bias -> coalesced global writes
#pragma unroll
    for (int i = 0; i < 4; i++)
#pragma unroll
        for (int j = 0; j < 2; j++)
            wmma::store_matrix_sync(st + (wr * 64 + i * 16) * LDS_ + wc * 32 + j * 16,
                                    acc[i][j], LDS_, wmma::mem_row_major);
    __syncthreads();

#pragma unroll
    for (int t = 0; t < 16; t++) {
        int f = tid + t * 256;           // 0..4095 float4s
        int row = f >> 5;
        int c4 = (f & 31) * 4;
        float4 v = *(float4*)&st[row * LDS_ + c4];
        float4 bv = *(const float4*)(bias + n0 + c4);
        v.x += bv.x; v.y += bv.y; v.z += bv.z; v.w += bv.w;
        int gm = m0 + row;
        int gc = n0 + c4;
        if (MODE == 1) {
            *(float4*)(out + (size_t)gm * NTOT + gc) = v;
        } else {
            int which = gc >> 10;            // 0=q,1=k,2=v
            int h = (gc >> 6) & 15;
            int d = gc & 63;                 // multiple of 4, never crosses head
            int bb = gm >> 11;
            int n = gm & 2047;
            float* dst = (which == 0) ? g_q : (which == 1) ? g_k : g_v;
            *(float4*)(dst + (((size_t)(bb * H_ + h)) * N_ + n) * (size_t)D_ + d) = v;
        }
    }
}

// ============================================================================
// Kernel 2: flash attention (verified SIMT fp32).  grid = (N/64, B*H), 256 thr.
// ============================================================================
#define ATTN_SMEM_FLOATS (64*64 + 64*68 + 64*64 + 64*64)
#define ATTN_SMEM_BYTES  (ATTN_SMEM_FLOATS * 4)

__global__ void __launch_bounds__(256)
attn_kernel(const int* __restrict__ mask)
{
    extern __shared__ float smf[];
    float* Qs = smf;
    float* Ks = Qs + 64 * 64;
    float* Vs = Ks + 64 * 68;
    float* Ps = Vs + 64 * 64;

    const int tid  = threadIdx.x;
    const int warp = tid >> 5;
    const int lane = tid & 31;
    const int bh = blockIdx.y;
    const int b  = bh >> 4;
    const int q0 = blockIdx.x * 64;
    const int h  = bh & 15;

    const float* qg  = g_q + ((size_t)bh * N_ + q0) * D_;
    const float* kgb = g_k + (size_t)bh * N_ * D_;
    const float* vgb = g_v + (size_t)bh * N_ * D_;
    const int*   mb  = mask + b * N_;

#pragma unroll
    for (int j = 0; j < 4; j++) {
        int f = tid + j * 256;
        int row = f >> 4;
        int c4 = (f & 15) * 4;
        *(float4*)&Qs[row * 64 + c4] = *(const float4*)(qg + row * D_ + c4);
    }

    const int r0 = warp * 8;
    const float NEG = neg_inf();
    float m_i[8], l_i[8], o0[8], o1[8];
#pragma unroll
    for (int i = 0; i < 8; i++) { m_i[i] = NEG; l_i[i] = 0.f; o0[i] = 0.f; o1[i] = 0.f; }

    for (int kt = 0; kt < N_ / 64; kt++) {
        __syncthreads();
        const float* kg = kgb + (size_t)kt * 64 * D_;
        const float* vg = vgb + (size_t)kt * 64 * D_;
#pragma unroll
        for (int j = 0; j < 4; j++) {
            int f = tid + j * 256;
            int row = f >> 4;
            int c4 = (f & 15) * 4;
            *(float4*)&Ks[row * 68 + c4] = *(const float4*)(kg + row * D_ + c4);
            *(float4*)&Vs[row * 64 + c4] = *(const float4*)(vg + row * D_ + c4);
        }
        __syncthreads();

        float s0[8], s1[8];
#pragma unroll
        for (int i = 0; i < 8; i++) { s0[i] = 0.f; s1[i] = 0.f; }
#pragma unroll
        for (int d4 = 0; d4 < 16; d4++) {
            float4 kv0 = *(float4*)&Ks[lane * 68 + d4 * 4];
            float4 kv1 = *(float4*)&Ks[(lane + 32) * 68 + d4 * 4];
#pragma unroll
            for (int i = 0; i < 8; i++) {
                float4 qv = *(float4*)&Qs[(r0 + i) * 64 + d4 * 4];
                s0[i] = fmaf(qv.x, kv0.x, fmaf(qv.y, kv0.y,
                        fmaf(qv.z, kv0.z, fmaf(qv.w, kv0.w, s0[i]))));
                s1[i] = fmaf(qv.x, kv1.x, fmaf(qv.y, kv1.y,
                        fmaf(qv.z, kv1.z, fmaf(qv.w, kv1.w, s1[i]))));
            }
        }

        const int mk0 = mb[kt * 64 + lane];
        const int mk1 = mb[kt * 64 + lane + 32];

#pragma unroll
        for (int i = 0; i < 8; i++) {
            float a0 = mk0 ? s0[i] * 0.5f : NEG;
            float a1 = mk1 ? s1[i] * 0.5f : NEG;
            float rm = fmaxf(a0, a1);
#pragma unroll
            for (int off = 16; off > 0; off >>= 1)
                rm = fmaxf(rm, __shfl_xor_sync(0xffffffffu, rm, off));
            float mn = fmaxf(m_i[i], rm);
            float p0 = (mn == NEG) ? 0.f : __expf(a0 - mn);
            float p1 = (mn == NEG) ? 0.f : __expf(a1 - mn);
            float corr = (m_i[i] == NEG) ? 0.f : __expf(m_i[i] - mn);
            float rs = p0 + p1;
#pragma unroll
            for (int off = 16; off > 0; off >>= 1)
                rs += __shfl_xor_sync(0xffffffffu, rs, off);
            l_i[i] = l_i[i] * corr + rs;
            o0[i] *= corr;
            o1[i] *= corr;
            m_i[i] = mn;
            Ps[(r0 + i) * 64 + lane]      = p0;
            Ps[(r0 + i) * 64 + lane + 32] = p1;
        }
        __syncwarp();

#pragma unroll
        for (int k4 = 0; k4 < 16; k4++) {
            float v0[4], v1[4];
#pragma unroll
            for (int q = 0; q < 4; q++) {
                v0[q] = Vs[(k4 * 4 + q) * 64 + lane];
                v1[q] = Vs[(k4 * 4 + q) * 64 + lane + 32];
            }
#pragma unroll
            for (int i = 0; i < 8; i++) {
                float4 pv = *(float4*)&Ps[(r0 + i) * 64 + k4 * 4];
                o0[i] = fmaf(pv.x, v0[0], fmaf(pv.y, v0[1],
                        fmaf(pv.z, v0[2], fmaf(pv.w, v0[3], o0[i]))));
                o1[i] = fmaf(pv.x, v1[0], fmaf(pv.y, v1[1],
                        fmaf(pv.z, v1[2], fmaf(pv.w, v1[3], o1[i]))));
            }
        }
    }

#pragma unroll
    for (int i = 0; i < 8; i++) {
        float inv = (l_i[i] > 0.f) ? (1.0f / l_i[i]) : 0.f;
        size_t row = ((size_t)(b * N_ + q0 + r0 + i)) * E_ + h * D_;
        g_o[row + lane]      = o0[i] * inv;
        g_o[row + lane + 32] = o1[i] * inv;
    }
}

// ============================================================================
extern "C" void kernel_launch(void* const* d_in, const int* in_sizes, int n_in,
                              void* d_out, int out_size)
{
    const float* x     = (const float*)d_in[0];
    const int*   mask  = (const int*)  d_in[1];
    const float* w_qkv = (const float*)d_in[2];
    const float* b_qkv = (const float*)d_in[3];
    const float* w_out = (const float*)d_in[4];
    const float* b_out = (const float*)d_in[5];
    float* out = (float*)d_out;

    cudaFuncSetAttribute(attn_kernel,
                         cudaFuncAttributeMaxDynamicSharedMemorySize, ATTN_SMEM_BYTES);
    cudaFuncSetAttribute(tc_gemm<0>,
                         cudaFuncAttributeMaxDynamicSharedMemorySize, GT_SMEM_BYTES);
    cudaFuncSetAttribute(tc_gemm<1>,
                         cudaFuncAttributeMaxDynamicSharedMemorySize, GT_SMEM_BYTES);

    // 0) precision-split conversions (inputs are real device ptrs; outputs are
    //    device globals bound inside the kernels)
    int n4x = M_ * E_ / 4;
    convert_hl<0><<<(n4x + 255) / 256, 256>>>(x, n4x);
    transpose_convert<0><<<dim3(3 * E_ / 32, E_ / 32), dim3(32, 8)>>>(w_qkv, E_, 3 * E_);
    transpose_convert<1><<<dim3(E_ / 32, E_ / 32), dim3(32, 8)>>>(w_out, E_, E_);

    // 1) QKV projection (WMMA bf16x3) + head scatter
    tc_gemm<0><<<dim3(3 * E_ / 128, M_ / 128), 256, GT_SMEM_BYTES>>>(b_qkv, nullptr);

    // 2) flash attention (fp32 SIMT)
    attn_kernel<<<dim3(N_ / 64, BH_), 256, ATTN_SMEM_BYTES>>>(mask);

    // 3) convert attention output, then out-projection (WMMA bf16x3)
    convert_hl<1><<<(n4x + 255) / 256, 256>>>(nullptr, n4x);
    tc_gemm<1><<<dim3(E_ / 128, M_ / 128), 256, GT_SMEM_BYTES>>>(b_out, out);
}

// round 14
// speedup vs baseline: 2.3397x; 1.7506x over previous
#include <cuda_runtime.h>
#include <cuda_bf16.h>
#include <mma.h>
#include <cstdint>

using namespace nvcuda;

// Problem constants
#define B_  4
#define N_  2048
#define E_  1024
#define H_  16
#define D_  64
#define BH_ (B_*H_)          // 64
#define M_  (B_*N_)          // 8192
#define K_  1024

// ---------------- scratch (device globals; no allocations allowed) ----------
// Only referenced from DEVICE code (host-side symbol use = ATS-readable host
// shadow = silent zeros; round-8 bug).
__device__ __nv_bfloat16 g_qh[(size_t)BH_ * N_ * D_];   // [bh][n][d]
__device__ __nv_bfloat16 g_ql[(size_t)BH_ * N_ * D_];
__device__ __nv_bfloat16 g_kh[(size_t)BH_ * N_ * D_];
__device__ __nv_bfloat16 g_kl[(size_t)BH_ * N_ * D_];
__device__ __nv_bfloat16 g_vth[(size_t)BH_ * D_ * N_];  // [bh][d][n]  (transposed)
__device__ __nv_bfloat16 g_vtl[(size_t)BH_ * D_ * N_];
__device__ __nv_bfloat16 g_oh[(size_t)M_ * K_];         // [b*N+n][h*64+d]
__device__ __nv_bfloat16 g_ol[(size_t)M_ * K_];

__device__ __nv_bfloat16 g_xh[(size_t)M_ * K_];
__device__ __nv_bfloat16 g_xl[(size_t)M_ * K_];
__device__ __nv_bfloat16 g_wqh[(size_t)3 * E_ * K_];    // [3072][1024]
__device__ __nv_bfloat16 g_wql[(size_t)3 * E_ * K_];
__device__ __nv_bfloat16 g_woh[(size_t)E_ * K_];
__device__ __nv_bfloat16 g_wol[(size_t)E_ * K_];

__device__ __forceinline__ float neg_inf() { return __int_as_float(0xff800000); }

__device__ __forceinline__ uint32_t pack_bf16(float x, float y) {
    __nv_bfloat162 t; t.x = __float2bfloat16(x); t.y = __float2bfloat16(y);
    return *(uint32_t*)&t;
}
__device__ __forceinline__ void split_hl(float x, __nv_bfloat16& h, __nv_bfloat16& l) {
    h = __float2bfloat16(x);
    l = __float2bfloat16(x - __bfloat162float(h));
}

// mma.sync m16n8k16 row.col bf16 -> fp32 (sm_80+ feature, valid on plain sm_103)
__device__ __forceinline__ void mma16816(float* c, uint32_t a0, uint32_t a1,
                                         uint32_t a2, uint32_t a3,
                                         uint32_t b0, uint32_t b1) {
    asm volatile(
        "mma.sync.aligned.m16n8k16.row.col.f32.bf16.bf16.f32 "
        "{%0,%1,%2,%3}, {%4,%5,%6,%7}, {%8,%9}, {%0,%1,%2,%3};"
        : "+f"(c[0]), "+f"(c[1]), "+f"(c[2]), "+f"(c[3])
        : "r"(a0), "r"(a1), "r"(a2), "r"(a3), "r"(b0), "r"(b1));
}

// ============================================================================
// Conversion kernels
// ============================================================================
__global__ void __launch_bounds__(256)
convert_hl_x(const float* __restrict__ X, int n4)
{
    int i = blockIdx.x * 256 + threadIdx.x;
    if (i >= n4) return;
    float4 v = ((const float4*)X)[i];
    __nv_bfloat16 h0, h1, h2, h3, l0, l1, l2, l3;
    split_hl(v.x, h0, l0); split_hl(v.y, h1, l1);
    split_hl(v.z, h2, l2); split_hl(v.w, h3, l3);
    __nv_bfloat162 H01{h0, h1}, H23{h2, h3}, L01{l0, l1}, L23{l2, l3};
    ((__nv_bfloat162*)g_xh)[2*i]   = H01;
    ((__nv_bfloat162*)g_xh)[2*i+1] = H23;
    ((__nv_bfloat162*)g_xl)[2*i]   = L01;
    ((__nv_bfloat162*)g_xl)[2*i+1] = L23;
}

// W [R][C] row-major fp32 -> [C][R] bf16 hi/lo.  DST 0: wq, DST 1: wo.
template <int DST>
__global__ void __launch_bounds__(256)
transpose_convert(const float* __restrict__ W, int R, int C)
{
    __nv_bfloat16* Th = (DST == 0) ? g_wqh : g_woh;
    __nv_bfloat16* Tl = (DST == 0) ? g_wql : g_wol;
    __shared__ float t[32][33];
    int c0 = blockIdx.x * 32, r0 = blockIdx.y * 32;
    int tx = threadIdx.x, ty = threadIdx.y;     // 32 x 8
#pragma unroll
    for (int i = 0; i < 32; i += 8)
        t[ty + i][tx] = W[(size_t)(r0 + ty + i) * C + c0 + tx];
    __syncthreads();
#pragma unroll
    for (int i = 0; i < 32; i += 8) {
        float v = t[tx][ty + i];
        __nv_bfloat16 h, l; split_hl(v, h, l);
        size_t o = (size_t)(c0 + ty + i) * R + r0 + tx;
        Th[o] = h; Tl[o] = l;
    }
}

// ============================================================================
// WMMA bf16x3 GEMM (verified R13).  MODE 0: X@Wqkv -> q/k/v hi-lo (V transposed)
//                                   MODE 1: O@Wout -> out (fp32 row-major)
// ============================================================================
#define LDT 40
#define TILE_ELEMS (128 * LDT)
#define LDS_ 132
#define GT_SMEM_BYTES (128 * LDS_ * 4)

template <int MODE>
__global__ void __launch_bounds__(256, 2)
tc_gemm(const float* __restrict__ bias, float* __restrict__ out)
{
    const __nv_bfloat16* Ah = (MODE == 0) ? g_xh : g_oh;
    const __nv_bfloat16* Al = (MODE == 0) ? g_xl : g_ol;
    const __nv_bfloat16* Bh = (MODE == 0) ? g_wqh : g_woh;
    const __nv_bfloat16* Bl = (MODE == 0) ? g_wql : g_wol;
    const int NTOT = (MODE == 0) ? 3 * E_ : E_;

    extern __shared__ __align__(16) char smem[];
    __nv_bfloat16* sAh = (__nv_bfloat16*)smem;
    __nv_bfloat16* sAl = sAh + TILE_ELEMS;
    __nv_bfloat16* sBh = sAl + TILE_ELEMS;
    __nv_bfloat16* sBl = sBh + TILE_ELEMS;
    float* st = (float*)smem;

    const int tid = threadIdx.x;
    const int wid = tid >> 5;
    const int wr = wid & 1;
    const int wc = wid >> 1;
    const int m0 = blockIdx.y * 128;
    const int n0 = blockIdx.x * 128;

    wmma::fragment<wmma::accumulator, 16, 16, 16, float> acc[4][2];
#pragma unroll
    for (int i = 0; i < 4; i++)
#pragma unroll
        for (int j = 0; j < 2; j++) wmma::fill_fragment(acc[i][j], 0.0f);

    for (int k0 = 0; k0 < K_; k0 += 32) {
#pragma unroll
        for (int t = 0; t < 2; t++) {
            int f = tid + t * 256;
            int row = f >> 2;
            int seg = f & 3;
            size_t ga = (size_t)(m0 + row) * K_ + k0 + seg * 8;
            size_t gb = (size_t)(n0 + row) * K_ + k0 + seg * 8;
            *(uint4*)(sAh + row * LDT + seg * 8) = *(const uint4*)(Ah + ga);
            *(uint4*)(sAl + row * LDT + seg * 8) = *(const uint4*)(Al + ga);
            *(uint4*)(sBh + row * LDT + seg * 8) = *(const uint4*)(Bh + gb);
            *(uint4*)(sBl + row * LDT + seg * 8) = *(const uint4*)(Bl + gb);
        }
        __syncthreads();

#pragma unroll
        for (int ks = 0; ks < 2; ks++) {
            wmma::fragment<wmma::matrix_b, 16, 16, 16, __nv_bfloat16, wmma::col_major> bh[2], bl[2];
#pragma unroll
            for (int j = 0; j < 2; j++) {
                wmma::load_matrix_sync(bh[j], sBh + (wc * 32 + j * 16) * LDT + ks * 16, LDT);
                wmma::load_matrix_sync(bl[j], sBl + (wc * 32 + j * 16) * LDT + ks * 16, LDT);
            }
#pragma unroll
            for (int i = 0; i < 4; i++) {
                wmma::fragment<wmma::matrix_a, 16, 16, 16, __nv_bfloat16, wmma::row_major> ah, al;
                wmma::load_matrix_sync(ah, sAh + (wr * 64 + i * 16) * LDT + ks * 16, LDT);
                wmma::load_matrix_sync(al, sAl + (wr * 64 + i * 16) * LDT + ks * 16, LDT);
#pragma unroll
                for (int j = 0; j < 2; j++) {
                    wmma::mma_sync(acc[i][j], ah, bh[j], acc[i][j]);
                    wmma::mma_sync(acc[i][j], ah, bl[j], acc[i][j]);
                    wmma::mma_sync(acc[i][j], al, bh[j], acc[i][j]);
                }
            }
        }
        __syncthreads();
    }

#pragma unroll
    for (int i = 0; i < 4; i++)
#pragma unroll
        for (int j = 0; j < 2; j++)
            wmma::store_matrix_sync(st + (wr * 64 + i * 16) * LDS_ + wc * 32 + j * 16,
                                    acc[i][j], LDS_, wmma::mem_row_major);
    __syncthreads();

#pragma unroll
    for (int t = 0; t < 16; t++) {
        int f = tid + t * 256;
        int row = f >> 5;
        int c4 = (f & 31) * 4;
        float4 v = *(float4*)&st[row * LDS_ + c4];
        float4 bv = *(const float4*)(bias + n0 + c4);
        v.x += bv.x; v.y += bv.y; v.z += bv.z; v.w += bv.w;
        int gm = m0 + row;
        int gc = n0 + c4;
        if (MODE == 1) {
            *(float4*)(out + (size_t)gm * NTOT + gc) = v;
        } else {
            int which = gc >> 10;            // 0=q,1=k,2=v
            int h = (gc >> 6) & 15;
            int d = gc & 63;                 // multiple of 4
            int bb = gm >> 11;
            int n = gm & 2047;
            int bhh = bb * H_ + h;
            __nv_bfloat16 h0, h1, h2, h3, l0, l1, l2, l3;
            split_hl(v.x, h0, l0); split_hl(v.y, h1, l1);
            split_hl(v.z, h2, l2); split_hl(v.w, h3, l3);
            if (which == 2) {
                // V transposed: [bh][d][n], scattered 2B stores (one-time)
                size_t base = ((size_t)bhh * D_ + d) * N_ + n;
                g_vth[base]          = h0; g_vtl[base]          = l0;
                g_vth[base + N_]     = h1; g_vtl[base + N_]     = l1;
                g_vth[base + 2*N_]   = h2; g_vtl[base + 2*N_]   = l2;
                g_vth[base + 3*N_]   = h3; g_vtl[base + 3*N_]   = l3;
            } else {
                __nv_bfloat16* dh = (which == 0) ? g_qh : g_kh;
                __nv_bfloat16* dl = (which == 0) ? g_ql : g_kl;
                size_t base = ((size_t)bhh * N_ + n) * D_ + d;
                __nv_bfloat162 H01{h0, h1}, H23{h2, h3}, L01{l0, l1}, L23{l2, l3};
                *(__nv_bfloat162*)(dh + base)     = H01;
                *(__nv_bfloat162*)(dh + base + 2) = H23;
                *(__nv_bfloat162*)(dl + base)     = L01;
                *(__nv_bfloat162*)(dl + base + 2) = L23;
            }
        }
    }
}

// ============================================================================
// Flash attention on mma.sync bf16x3.
//   grid = (N/128, BH), 256 threads = 8 warps x 16 query rows.
//   K-tile = 64 keys.  S split: QhKh+QhKl+QlKh.  PV split: PhVh+PhVl+PlVh.
//   P rebuilt in-register from S accumulators (C-frag pair == A-frag layout).
// ============================================================================
#define LKV 72   // smem row stride (bf16 elems)

__global__ void __launch_bounds__(256)
attn_kernel(const int* __restrict__ mask)
{
    __shared__ __nv_bfloat16 Ksh[64][LKV], Ksl[64][LKV];
    __shared__ __nv_bfloat16 Vth[64][LKV], Vtl[64][LKV];   // [dim][key]
    __shared__ float maskf[64];

    const int tid  = threadIdx.x;
    const int warp = tid >> 5;
    const int lane = tid & 31;
    const int bh = blockIdx.y;
    const int b  = bh >> 4;
    const int h  = bh & 15;
    const int q0 = blockIdx.x * 128;
    const int r0 = warp * 16;
    const int ra = lane >> 2;          // row within 16 (second row = ra+8)
    const int cp = (lane & 3) * 2;     // col pair base

    const float NEG = neg_inf();

    // ---- Q fragments (registers, hi/lo), A-layout for m16n8k16 ----
    const __nv_bfloat16* qbh = g_qh + ((size_t)bh * N_ + q0 + r0) * D_;
    const __nv_bfloat16* qbl = g_ql + ((size_t)bh * N_ + q0 + r0) * D_;
    uint32_t qh[4][4], ql[4][4];
#pragma unroll
    for (int k = 0; k < 4; k++) {
        qh[k][0] = *(const uint32_t*)(qbh + ra * D_ + k * 16 + cp);
        qh[k][1] = *(const uint32_t*)(qbh + (ra + 8) * D_ + k * 16 + cp);
        qh[k][2] = *(const uint32_t*)(qbh + ra * D_ + k * 16 + cp + 8);
        qh[k][3] = *(const uint32_t*)(qbh + (ra + 8) * D_ + k * 16 + cp + 8);
        ql[k][0] = *(const uint32_t*)(qbl + ra * D_ + k * 16 + cp);
        ql[k][1] = *(const uint32_t*)(qbl + (ra + 8) * D_ + k * 16 + cp);
        ql[k][2] = *(const uint32_t*)(qbl + ra * D_ + k * 16 + cp + 8);
        ql[k][3] = *(const uint32_t*)(qbl + (ra + 8) * D_ + k * 16 + cp + 8);
    }

    float o[8][4];
#pragma unroll
    for (int t = 0; t < 8; t++)
#pragma unroll
        for (int j = 0; j < 4; j++) o[t][j] = 0.f;
    float m0v = NEG, m1v = NEG, l0s = 0.f, l1s = 0.f;

    const __nv_bfloat16* kgh = g_kh + (size_t)bh * N_ * D_;
    const __nv_bfloat16* kgl = g_kl + (size_t)bh * N_ * D_;
    const __nv_bfloat16* vgh = g_vth + (size_t)bh * D_ * N_;
    const __nv_bfloat16* vgl = g_vtl + (size_t)bh * D_ * N_;
    const int* mb = mask + b * N_;

    for (int kt = 0; kt < N_ / 64; kt++) {
        __syncthreads();
        // load K tile [key][d] and V tile [d][key] (both 64x64 bf16 hi/lo)
#pragma unroll
        for (int j = 0; j < 4; j++) {
            int f = tid + j * 256;
            int row = f >> 4;
            int c = (f & 15) * 4;
            *(uint2*)&Ksh[row][c] = *(const uint2*)(kgh + (size_t)(kt * 64 + row) * D_ + c);
            *(uint2*)&Ksl[row][c] = *(const uint2*)(kgl + (size_t)(kt * 64 + row) * D_ + c);
            *(uint2*)&Vth[row][c] = *(const uint2*)(vgh + (size_t)row * N_ + kt * 64 + c);
            *(uint2*)&Vtl[row][c] = *(const uint2*)(vgl + (size_t)row * N_ + kt * 64 + c);
        }
        if (tid < 64) maskf[tid] = mb[kt * 64 + tid] ? 0.f : NEG;
        __syncthreads();

        // ---- S = Q @ K^T  (bf16x3) ----
        float s[8][4];
#pragma unroll
        for (int t = 0; t < 8; t++)
#pragma unroll
            for (int j = 0; j < 4; j++) s[t][j] = 0.f;
#pragma unroll
        for (int t = 0; t < 8; t++) {
            int key = ra + t * 8;
#pragma unroll
            for (int k = 0; k < 4; k++) {
                uint32_t b0h = *(const uint32_t*)&Ksh[key][cp + k * 16];
                uint32_t b1h = *(const uint32_t*)&Ksh[key][cp + k * 16 + 8];
                uint32_t b0l = *(const uint32_t*)&Ksl[key][cp + k * 16];
                uint32_t b1l = *(const uint32_t*)&Ksl[key][cp + k * 16 + 8];
                mma16816(s[t], qh[k][0], qh[k][1], qh[k][2], qh[k][3], b0h, b1h);
                mma16816(s[t], qh[k][0], qh[k][1], qh[k][2], qh[k][3], b0l, b1l);
                mma16816(s[t], ql[k][0], ql[k][1], ql[k][2], ql[k][3], b0h, b1h);
            }
        }

        // ---- scale + mask + online softmax ----
#pragma unroll
        for (int t = 0; t < 8; t++) {
            float mk0 = maskf[t * 8 + cp];
            float mk1 = maskf[t * 8 + cp + 1];
            s[t][0] = s[t][0] * 0.5f + mk0;
            s[t][1] = s[t][1] * 0.5f + mk1;
            s[t][2] = s[t][2] * 0.5f + mk0;
            s[t][3] = s[t][3] * 0.5f + mk1;
        }
        float ma = NEG, mbv = NEG;
#pragma unroll
        for (int t = 0; t < 8; t++) {
            ma  = fmaxf(ma,  fmaxf(s[t][0], s[t][1]));
            mbv = fmaxf(mbv, fmaxf(s[t][2], s[t][3]));
        }
        ma  = fmaxf(ma,  __shfl_xor_sync(0xffffffffu, ma, 1));
        ma  = fmaxf(ma,  __shfl_xor_sync(0xffffffffu, ma, 2));
        mbv = fmaxf(mbv, __shfl_xor_sync(0xffffffffu, mbv, 1));
        mbv = fmaxf(mbv, __shfl_xor_sync(0xffffffffu, mbv, 2));
        float mna = fmaxf(m0v, ma);
        float mnb = fmaxf(m1v, mbv);
        float ca = (m0v == NEG) ? 0.f : __expf(m0v - mna);
        float cb = (m1v == NEG) ? 0.f : __expf(m1v - mnb);
        float suma = 0.f, sumb = 0.f;
        if (mna == NEG) {
#pragma unroll
            for (int t = 0; t < 8; t++) { s[t][0] = 0.f; s[t][1] = 0.f; }
        } else {
#pragma unroll
            for (int t = 0; t < 8; t++) {
                s[t][0] = __expf(s[t][0] - mna);
                s[t][1] = __expf(s[t][1] - mna);
                suma += s[t][0] + s[t][1];
            }
        }
        if (mnb == NEG) {
#pragma unroll
            for (int t = 0; t < 8; t++) { s[t][2] = 0.f; s[t][3] = 0.f; }
        } else {
#pragma unroll
            for (int t = 0; t < 8; t++) {
                s[t][2] = __expf(s[t][2] - mnb);
                s[t][3] = __expf(s[t][3] - mnb);
                sumb += s[t][2] + s[t][3];
            }
        }
        suma += __shfl_xor_sync(0xffffffffu, suma, 1);
        suma += __shfl_xor_sync(0xffffffffu, suma, 2);
        sumb += __shfl_xor_sync(0xffffffffu, sumb, 1);
        sumb += __shfl_xor_sync(0xffffffffu, sumb, 2);
        l0s = l0s * ca + suma;
        l1s = l1s * cb + sumb;
#pragma unroll
        for (int t = 0; t < 8; t++) {
            o[t][0] *= ca; o[t][1] *= ca;
            o[t][2] *= cb; o[t][3] *= cb;
        }
        m0v = mna; m1v = mnb;

        // ---- O += P @ V  (P from S accumulators, hi/lo split) ----
#pragma unroll
        for (int kp = 0; kp < 4; kp++) {
            int t0 = 2 * kp, t1 = t0 + 1;
            __nv_bfloat16 h0, h1, l0b, l1b;
            uint32_t pa[4], pl[4];
            split_hl(s[t0][0], h0, l0b); split_hl(s[t0][1], h1, l1b);
            pa[0] = pack_bf16(__bfloat162float(h0), __bfloat162float(h1));
            pl[0] = pack_bf16(__bfloat162float(l0b), __bfloat162float(l1b));
            split_hl(s[t0][2], h0, l0b); split_hl(s[t0][3], h1, l1b);
            pa[1] = pack_bf16(__bfloat162float(h0), __bfloat162float(h1));
            pl[1] = pack_bf16(__bfloat162float(l0b), __bfloat162float(l1b));
            split_hl(s[t1][0], h0, l0b); split_hl(s[t1][1], h1, l1b);
            pa[2] = pack_bf16(__bfloat162float(h0), __bfloat162float(h1));
            pl[2] = pack_bf16(__bfloat162float(l0b), __bfloat162float(l1b));
            split_hl(s[t1][2], h0, l0b); split_hl(s[t1][3], h1, l1b);
            pa[3] = pack_bf16(__bfloat162float(h0), __bfloat162float(h1));
            pl[3] = pack_bf16(__bfloat162float(l0b), __bfloat162float(l1b));
#pragma unroll
            for (int t = 0; t < 8; t++) {
                int dim = ra + t * 8;
                uint32_t b0h = *(const uint32_t*)&Vth[dim][cp + kp * 16];
                uint32_t b1h = *(const uint32_t*)&Vth[dim][cp + kp * 16 + 8];
                uint32_t b0l = *(const uint32_t*)&Vtl[dim][cp + kp * 16];
                uint32_t b1l = *(const uint32_t*)&Vtl[dim][cp + kp * 16 + 8];
                mma16816(o[t], pa[0], pa[1], pa[2], pa[3], b0h, b1h);
                mma16816(o[t], pa[0], pa[1], pa[2], pa[3], b0l, b1l);
                mma16816(o[t], pl[0], pl[1], pl[2], pl[3], b0h, b1h);
            }
        }
    }

    // ---- epilogue: normalize, split hi/lo, write g_oh/g_ol ----
    float inva = (l0s > 0.f) ? (1.0f / l0s) : 0.f;
    float invb = (l1s > 0.f) ? (1.0f / l1s) : 0.f;
    size_t rowa = ((size_t)(b * N_ + q0 + r0 + ra)) * E_ + h * D_;
    size_t rowb = rowa + (size_t)8 * E_;
#pragma unroll
    for (int t = 0; t < 8; t++) {
        int c = t * 8 + cp;
        float x0 = o[t][0] * inva, x1 = o[t][1] * inva;
        float x2 = o[t][2] * invb, x3 = o[t][3] * invb;
        __nv_bfloat16 hh, ll;
        __nv_bfloat16 h0, l0b, h1, l1b;
        split_hl(x0, h0, l0b); split_hl(x1, h1, l1b);
        *(uint32_t*)(g_oh + rowa + c) = pack_bf16(__bfloat162float(h0), __bfloat162float(h1));
        *(uint32_t*)(g_ol + rowa + c) = pack_bf16(__bfloat162float(l0b), __bfloat162float(l1b));
        split_hl(x2, h0, l0b); split_hl(x3, h1, l1b);
        *(uint32_t*)(g_oh + rowb + c) = pack_bf16(__bfloat162float(h0), __bfloat162float(h1));
        *(uint32_t*)(g_ol + rowb + c) = pack_bf16(__bfloat162float(l0b), __bfloat162float(l1b));
        (void)hh; (void)ll;
    }
}

// ============================================================================
extern "C" void kernel_launch(void* const* d_in, const int* in_sizes, int n_in,
                              void* d_out, int out_size)
{
    const float* x     = (const float*)d_in[0];
    const int*   mask  = (const int*)  d_in[1];
    const float* w_qkv = (const float*)d_in[2];
    const float* b_qkv = (const float*)d_in[3];
    const float* w_out = (const float*)d_in[4];
    const float* b_out = (const float*)d_in[5];
    float* out = (float*)d_out;

    cudaFuncSetAttribute(tc_gemm<0>,
                         cudaFuncAttributeMaxDynamicSharedMemorySize, GT_SMEM_BYTES);
    cudaFuncSetAttribute(tc_gemm<1>,
                         cudaFuncAttributeMaxDynamicSharedMemorySize, GT_SMEM_BYTES);

    // 0) precision-split conversions
    int n4x = M_ * E_ / 4;
    convert_hl_x<<<(n4x + 255) / 256, 256>>>(x, n4x);
    transpose_convert<0><<<dim3(3 * E_ / 32, E_ / 32), dim3(32, 8)>>>(w_qkv, E_, 3 * E_);
    transpose_convert<1><<<dim3(E_ / 32, E_ / 32), dim3(32, 8)>>>(w_out, E_, E_);

    // 1) QKV projection (WMMA bf16x3) -> q/k/v bf16 hi/lo (V transposed)
    tc_gemm<0><<<dim3(3 * E_ / 128, M_ / 128), 256, GT_SMEM_BYTES>>>(b_qkv, nullptr);

    // 2) flash attention on mma.sync bf16x3 -> g_oh/g_ol
    attn_kernel<<<dim3(N_ / 128, BH_), 256>>>(mask);

    // 3) output projection (WMMA bf16x3)
    tc_gemm<1><<<dim3(E_ / 128, M_ / 128), 256, GT_SMEM_BYTES>>>(b_out, out);
}